// round 2
// baseline (speedup 1.0000x reference)
#include <cuda_runtime.h>

// CRF forward partition function, linear-domain reformulation.
// B=512 batches, T=1024 steps, K=48 tags.
// One warp per batch; lane L owns output rows i1=L and i2=L+32 (lanes 0..15).
// E rows held in registers as packed f32x2 (i1,i2); p held duplicated in
// shared so ld.shared.v2.u64 yields ready-packed (p_j,p_j) multiplicands for
// fma.rn.f32x2. Per-step exponent renormalization (exact powers of 2) with
// one-step lag; PAD chain tracked analytically (exactly decoupled in fp32).

#define KK 48
#define TT 1024
#define BB 512
#define PAD_TAG 45
#define START_TAG 46
#define STOP_TAG 47
#define NEGV (-10000.0f)
#define LOG2E 1.4426950408889634f
#define LN2F 0.6931471805599453f

__device__ __forceinline__ float ex2(float x) {
    float r; asm("ex2.approx.f32 %0, %1;" : "=f"(r) : "f"(x)); return r;
}
__device__ __forceinline__ float lg2(float x) {
    float r; asm("lg2.approx.f32 %0, %1;" : "=f"(r) : "f"(x)); return r;
}
__device__ __forceinline__ unsigned long long pk2(float lo, float hi) {
    unsigned long long r;
    asm("mov.b64 %0, {%1, %2};" : "=l"(r) : "f"(lo), "f"(hi));
    return r;
}
__device__ __forceinline__ void upk2(float& lo, float& hi, unsigned long long v) {
    asm("mov.b64 {%0, %1}, %2;" : "=f"(lo), "=f"(hi) : "l"(v));
}
__device__ __forceinline__ void ffma2(unsigned long long& acc,
                                      unsigned long long a, unsigned long long b) {
    asm("fma.rn.f32x2 %0, %1, %2, %0;" : "+l"(acc) : "l"(a), "l"(b));
}
__device__ __forceinline__ unsigned long long add2(unsigned long long a,
                                                   unsigned long long b) {
    unsigned long long r;
    asm("add.rn.f32x2 %0, %1, %2;" : "=l"(r) : "l"(a), "l"(b));
    return r;
}

__global__ __launch_bounds__(128, 1)
void crf_fwd_kernel(const float* __restrict__ h_tag,
                    const float* __restrict__ mask,
                    const float* __restrict__ trans,
                    float* __restrict__ out) {
    __shared__ __align__(16) float trs[KK * KK];
    __shared__ __align__(16) float pd[4][96];   // duplicated p pairs, per warp

    const int tid  = threadIdx.x;
    const int wid  = tid >> 5;
    const int lane = tid & 31;
    const int b    = blockIdx.x * 4 + wid;

    // Stage trans coalesced into shared.
    for (int i = tid; i < KK * KK; i += 128) trs[i] = trans[i];
    __syncthreads();

    const int  i1   = lane;
    const bool has2 = (lane < 16);
    const int  i2   = has2 ? (lane + 32) : 0;   // clamped index for safe loads

    // Build E rows in registers: Ep[j] = packed( exp2(trans[i1][j]*K2),
    //                                            exp2(trans[i2][j]*K2) )
    unsigned long long Ep[KK];
    float rs1 = 0.f, rs2 = 0.f, es1 = 0.f, es2 = 0.f;
#pragma unroll
    for (int j = 0; j < KK; ++j) {
        float e1 = ex2(trs[i1 * KK + j] * LOG2E);
        float e2 = has2 ? ex2(trs[i2 * KK + j] * LOG2E) : 0.f;
        Ep[j] = pk2(e1, e2);
        rs1 += e1; rs2 += e2;
        if (j == STOP_TAG) { es1 = e1; es2 = e2; }
    }
    const float ES1 = ex2(trs[STOP_TAG * KK + i1] * LOG2E);
    const float ES2 = has2 ? ex2(trs[STOP_TAG * KK + i2] * LOG2E) : 0.f;

    // Exact init at group scale C0 = NEG*log2e:
    // p_i(1) = g_i * ( [i != PAD] + rowsum_i - E[i][STOP] )
    const float base1 = ((i1 == PAD_TAG) ? 0.f : 1.f) + rs1 - es1;
    const float base2 = ((has2 && i2 == PAD_TAG) ? 0.f : 1.f) + rs2 - es2;

    const float* emb = h_tag + (size_t)b * TT * KK;
    float em1 = emb[i1];
    float em2 = has2 ? emb[i2] : 0.f;
    float p1 = ex2(em1 * LOG2E) * base1;
    float p2 = has2 ? (ex2(em2 * LOG2E) * base2) : 0.f;
    float padacc = em2;   // lane 13 (i2 == 45 == PAD) is the meaningful one

    float* pdw = pd[wid];
    *(unsigned long long*)&pdw[2 * i1] = pk2(p1, p1);
    if (has2) *(unsigned long long*)&pdw[2 * i2] = pk2(p2, p2);

    int c = 0, eprev;
    {
        float zp = __shfl_sync(0xffffffffu, p1, 0);
        int eb = (__float_as_int(zp) >> 23) & 255;
        eprev = (eb == 0) ? 0 : (eb - 127);
    }
    __syncwarp();

    // Depth-2 prefetch buffers (slot = t & 1).
    float nem1[2], nem2[2], nmk[2];
    {
        const float* e1p = emb + 1 * KK;
        const float* e2p = emb + 2 * KK;
        nem1[1] = e1p[i1]; nem2[1] = has2 ? e1p[i2] : 0.f;
        nem1[0] = e2p[i1]; nem2[0] = has2 ? e2p[i2] : 0.f;
        nmk[1] = mask[(size_t)b * TT + 1];
        nmk[0] = mask[(size_t)b * TT + 2];
    }

#pragma unroll 2
    for (int t = 1; t < TT; ++t) {
        const int sl = t & 1;
        const float cem1 = nem1[sl];
        const float cem2 = nem2[sl];
        const float cmk  = nmk[sl];

        int tp = t + 2; if (tp > TT - 1) tp = TT - 1;
        const float* ep = emb + (size_t)tp * KK;
        nem1[sl] = ep[i1];
        nem2[sl] = has2 ? ep[i2] : 0.f;
        nmk[sl]  = mask[(size_t)b * TT + tp];

        if (cmk != 0.0f) {
            const float ne = -(float)eprev;
            const float g1 = ex2(fmaf(cem1, LOG2E, ne));
            const float g2 = ex2(fmaf(cem2, LOG2E, ne));

            unsigned long long q0 = 0ull, q1 = 0ull, q2 = 0ull, q3 = 0ull;
#pragma unroll
            for (int j = 0; j < KK; j += 4) {
                ulonglong2 pA = *(const ulonglong2*)(pdw + 2 * j);
                ulonglong2 pB = *(const ulonglong2*)(pdw + 2 * j + 4);
                ffma2(q0, pA.x, Ep[j]);
                ffma2(q1, pA.y, Ep[j + 1]);
                ffma2(q2, pB.x, Ep[j + 2]);
                ffma2(q3, pB.y, Ep[j + 3]);
            }
            const unsigned long long qs = add2(add2(q0, q1), add2(q2, q3));
            float qa, qb; upk2(qa, qb, qs);

            p1 = qa * g1;
            p2 = qb * g2;
            *(unsigned long long*)&pdw[2 * i1] = pk2(p1, p1);
            if (has2) *(unsigned long long*)&pdw[2 * i2] = pk2(p2, p2);

            padacc += cem2;
            c += eprev;

            // Lagged exponent proxy: consumed next masked step; shfl latency
            // hides under the next step's FMA block.
            const float zp = __shfl_sync(0xffffffffu, p1, 0);
            const int eb = (__float_as_int(zp) >> 23) & 255;
            eprev = (eb == 0) ? 0 : (eb - 127);
        }
        __syncwarp();
    }

    // Final: main group  lse_j(score_j + trans[STOP][j])  at scale C,
    // merged with analytic PAD chain (+ trans[STOP][PAD] = NEG).
    float s = p1 * ES1 + (has2 ? p2 * ES2 : 0.f);
#pragma unroll
    for (int o = 16; o > 0; o >>= 1)
        s += __shfl_xor_sync(0xffffffffu, s, o);

    const float C     = NEGV * LOG2E + (float)c;
    const float main2 = C + lg2(s);
    const float padv  = __shfl_sync(0xffffffffu, padacc, 13);
    const float pad2  = (padv + NEGV) * LOG2E;
    const float hi = fmaxf(main2, pad2);
    const float lo = fminf(main2, pad2);
    const float ans2 = hi + lg2(1.0f + ex2(lo - hi));

    if (lane == 0) out[b] = ans2 * LN2F;
}

extern "C" void kernel_launch(void* const* d_in, const int* in_sizes, int n_in,
                              void* d_out, int out_size) {
    const float* h_tag = (const float*)d_in[0];
    const float* mask  = (const float*)d_in[1];
    const float* trans = (const float*)d_in[2];
    float* out = (float*)d_out;
    (void)in_sizes; (void)n_in; (void)out_size;
    crf_fwd_kernel<<<BB / 4, 128>>>(h_tag, mask, trans, out);
}

// round 3
// speedup vs baseline: 2.2190x; 2.2190x over previous
#include <cuda_runtime.h>
#include <cstdint>

// CRF forward partition function, linear-domain reformulation, R3.
// One warp per batch; lane L owns output rows i1=L and i2=L+32 (lanes 0..15).
// R3 changes vs R2:
//   * Deep emission/mask pipeline: cp.async 16-step chunks, double-buffered
//     in shared memory (global latency fully hidden; loop reads LDS only).
//   * Branchless step (selects on mask != 0) -- removes per-step BSSY/BSYNC.
//   * Matvec trimmed to 46 j-terms (E[:,PAD] = E[:,STOP] = 0 exactly).
// Numerics unchanged: per-step exact power-of-2 renorm with one-step lag,
// PAD chain decoupled analytically.

#define KK 48
#define TT 1024
#define BB 512
#define CH 16
#define NCHUNK (TT / CH)
#define PAD_TAG 45
#define STOP_TAG 47
#define NEGV (-10000.0f)
#define LOG2E 1.4426950408889634f
#define LN2F 0.6931471805599453f

__device__ __forceinline__ float ex2(float x) {
    float r; asm("ex2.approx.f32 %0, %1;" : "=f"(r) : "f"(x)); return r;
}
__device__ __forceinline__ float lg2(float x) {
    float r; asm("lg2.approx.f32 %0, %1;" : "=f"(r) : "f"(x)); return r;
}
__device__ __forceinline__ unsigned long long pk2(float lo, float hi) {
    unsigned long long r;
    asm("mov.b64 %0, {%1, %2};" : "=l"(r) : "f"(lo), "f"(hi));
    return r;
}
__device__ __forceinline__ void upk2(float& lo, float& hi, unsigned long long v) {
    asm("mov.b64 {%0, %1}, %2;" : "=f"(lo), "=f"(hi) : "l"(v));
}
__device__ __forceinline__ void ffma2(unsigned long long& acc,
                                      unsigned long long a, unsigned long long b) {
    asm("fma.rn.f32x2 %0, %1, %2, %0;" : "+l"(acc) : "l"(a), "l"(b));
}
__device__ __forceinline__ unsigned long long add2(unsigned long long a,
                                                   unsigned long long b) {
    unsigned long long r;
    asm("add.rn.f32x2 %0, %1, %2;" : "=l"(r) : "l"(a), "l"(b));
    return r;
}
__device__ __forceinline__ void cpasync16(uint32_t saddr, const void* gaddr) {
    asm volatile("cp.async.cg.shared.global [%0], [%1], 16;"
                 :: "r"(saddr), "l"(gaddr));
}
__device__ __forceinline__ void cpcommit() {
    asm volatile("cp.async.commit_group;");
}
__device__ __forceinline__ void cpwait1() {
    asm volatile("cp.async.wait_group 1;");
}

__global__ __launch_bounds__(128, 1)
void crf_fwd_kernel(const float* __restrict__ h_tag,
                    const float* __restrict__ mask,
                    const float* __restrict__ trans,
                    float* __restrict__ out) {
    __shared__ __align__(16) float trs[KK * KK];
    __shared__ __align__(16) float pd[4][96];              // duplicated p pairs
    __shared__ __align__(16) float sm_em[4][2][CH * KK];   // emission chunks
    __shared__ __align__(16) float sm_mk[4][2][CH];        // mask chunks

    const int tid  = threadIdx.x;
    const int wid  = tid >> 5;
    const int lane = tid & 31;
    const int b    = blockIdx.x * 4 + wid;

    const float* emb = h_tag + (size_t)b * TT * KK;
    const float* mkb = mask + (size_t)b * TT;

    // ---- deep prefetch: issue chunks 0 and 1 immediately ----
    auto issue_chunk = [&](int cc) {
        const float* src = emb + cc * (CH * KK);
        uint32_t dst = (uint32_t)__cvta_generic_to_shared(&sm_em[wid][cc & 1][0]);
#pragma unroll
        for (int it = 0; it < (CH * KK) / (32 * 4); ++it) {   // 6 iters
            int off = (it * 32 + lane) * 4;                   // float index
            cpasync16(dst + (uint32_t)off * 4u, src + off);
        }
        if (lane < CH / 4) {
            uint32_t md = (uint32_t)__cvta_generic_to_shared(&sm_mk[wid][cc & 1][0]);
            cpasync16(md + (uint32_t)lane * 16u, mkb + cc * CH + lane * 4);
        }
        cpcommit();
    };
    issue_chunk(0);
    issue_chunk(1);

    // Stage trans coalesced into shared (overlaps with cp.async flight time).
    for (int i = tid; i < KK * KK; i += 128) trs[i] = trans[i];
    __syncthreads();

    const int  i1   = lane;
    const bool has2 = (lane < 16);
    const int  i2   = has2 ? (lane + 32) : 0;   // clamped for safe loads

    // Build E rows in registers: Ep[j] = packed(exp(trans[i1][j]), exp(trans[i2][j]))
    unsigned long long Ep[KK - 1];              // j = 0..46 (47 never used)
    float rs1 = 0.f, rs2 = 0.f, es1 = 0.f, es2 = 0.f;
#pragma unroll
    for (int j = 0; j < KK; ++j) {
        float e1 = ex2(trs[i1 * KK + j] * LOG2E);
        float e2 = has2 ? ex2(trs[i2 * KK + j] * LOG2E) : 0.f;
        if (j < KK - 1) Ep[j] = pk2(e1, e2);
        rs1 += e1; rs2 += e2;
        if (j == STOP_TAG) { es1 = e1; es2 = e2; }
    }
    const float ES1 = ex2(trs[STOP_TAG * KK + i1] * LOG2E);
    const float ES2 = has2 ? ex2(trs[STOP_TAG * KK + i2] * LOG2E) : 0.f;

    // Exact init at group scale C0 = NEG*log2e:
    // p_i(1) = g_i * ( [i != PAD] + rowsum_i - E[i][STOP] )
    const float base1 = ((i1 == PAD_TAG) ? 0.f : 1.f) + rs1 - es1;
    const float base2 = ((has2 && i2 == PAD_TAG) ? 0.f : 1.f) + rs2 - es2;

    float em1 = emb[i1];
    float em2 = has2 ? emb[i2] : 0.f;
    float p1 = ex2(em1 * LOG2E) * base1;
    float p2 = has2 ? (ex2(em2 * LOG2E) * base2) : 0.f;
    float padacc = em2;                 // lane 13 (i2==45==PAD) is meaningful

    float* pdw = pd[wid];
    *(unsigned long long*)&pdw[2 * i1] = pk2(p1, p1);
    if (has2) *(unsigned long long*)&pdw[2 * i2] = pk2(p2, p2);

    int c = 0, eprev;
    {
        float zp = __shfl_sync(0xffffffffu, p1, 0);
        int eb = (__float_as_int(zp) >> 23) & 255;
        eprev = (eb == 0) ? 0 : (eb - 127);
    }
    __syncwarp();

    // ---- the branchless scan step (reads emissions/mask from shared) ----
    auto step = [&](const float* __restrict__ embuf,
                    const float* __restrict__ mkbuf, int tt) {
        const float cem1 = embuf[tt * KK + i1];
        const float cem2 = embuf[tt * KK + i2];
        const float cmk  = mkbuf[tt];
        const bool  m    = (cmk != 0.0f);

        const float ne = -(float)eprev;
        const float g1 = ex2(fmaf(cem1, LOG2E, ne));
        const float g2 = ex2(fmaf(cem2, LOG2E, ne));

        unsigned long long q0 = 0ull, q1 = 0ull, q2 = 0ull, q3 = 0ull;
#pragma unroll
        for (int j = 0; j < 44; j += 4) {
            ulonglong2 pA = *(const ulonglong2*)(pdw + 2 * j);
            ulonglong2 pB = *(const ulonglong2*)(pdw + 2 * j + 4);
            ffma2(q0, pA.x, Ep[j]);
            ffma2(q1, pA.y, Ep[j + 1]);
            ffma2(q2, pB.x, Ep[j + 2]);
            ffma2(q3, pB.y, Ep[j + 3]);
        }
        {   // tail: j = 44 and j = 46 (cols 45/PAD and 47/STOP are exactly 0)
            unsigned long long p44 = *(const unsigned long long*)(pdw + 88);
            unsigned long long p46 = *(const unsigned long long*)(pdw + 92);
            ffma2(q0, p44, Ep[44]);
            ffma2(q1, p46, Ep[46]);
        }
        const unsigned long long qs = add2(add2(q0, q1), add2(q2, q3));
        float qa, qb; upk2(qa, qb, qs);

        const float p1n = qa * g1;
        const float p2n = qb * g2;
        p1 = m ? p1n : p1;
        p2 = m ? p2n : p2;
        padacc += m ? cem2 : 0.f;
        c      += m ? eprev : 0;

        // Lagged exponent proxy (consumed next step; latency hidden).
        const float zp = __shfl_sync(0xffffffffu, p1, 0);

        *(unsigned long long*)&pdw[2 * i1] = pk2(p1, p1);
        if (has2) *(unsigned long long*)&pdw[2 * i2] = pk2(p2, p2);
        __syncwarp();

        const int eb = (__float_as_int(zp) >> 23) & 255;
        eprev = (eb == 0) ? 0 : (eb - 127);
    };

    // ---- chunk 0 (steps 1..15; step 0 handled by the init above) ----
    {
        cpwait1();        // group 0 complete (only group 1 may remain pending)
        __syncwarp();
        const float* embuf = sm_em[wid][0];
        const float* mkbuf = sm_mk[wid][0];
#pragma unroll 5
        for (int tt = 1; tt < CH; ++tt) step(embuf, mkbuf, tt);
        issue_chunk(2);
    }

    // ---- chunks 1..63 ----
    for (int cc = 1; cc < NCHUNK; ++cc) {
        cpwait1();        // chunk cc resident (only cc+1 may remain pending)
        __syncwarp();
        const float* embuf = sm_em[wid][cc & 1];
        const float* mkbuf = sm_mk[wid][cc & 1];
#pragma unroll 4
        for (int tt = 0; tt < CH; ++tt) step(embuf, mkbuf, tt);
        if (cc + 2 < NCHUNK) issue_chunk(cc + 2);
    }

    // ---- final: lse_j(score_j + trans[STOP][j]) at scale C, merged with
    //      the analytic PAD chain (+ trans[STOP][PAD] = NEG). ----
    float s = p1 * ES1 + (has2 ? p2 * ES2 : 0.f);
#pragma unroll
    for (int o = 16; o > 0; o >>= 1)
        s += __shfl_xor_sync(0xffffffffu, s, o);

    const float C     = NEGV * LOG2E + (float)c;
    const float main2 = C + lg2(s);
    const float padv  = __shfl_sync(0xffffffffu, padacc, 13);
    const float pad2  = (padv + NEGV) * LOG2E;
    const float hi = fmaxf(main2, pad2);
    const float lo = fminf(main2, pad2);
    const float ans2 = hi + lg2(1.0f + ex2(lo - hi));

    if (lane == 0) out[b] = ans2 * LN2F;
}

extern "C" void kernel_launch(void* const* d_in, const int* in_sizes, int n_in,
                              void* d_out, int out_size) {
    const float* h_tag = (const float*)d_in[0];
    const float* mask  = (const float*)d_in[1];
    const float* trans = (const float*)d_in[2];
    float* out = (float*)d_out;
    (void)in_sizes; (void)n_in; (void)out_size;
    crf_fwd_kernel<<<BB / 4, 128>>>(h_tag, mask, trans, out);
}